// round 13
// baseline (speedup 1.0000x reference)
#include <cuda_runtime.h>
#include <cuda_bf16.h>
#include <math.h>
#include <stdint.h>

namespace {
constexpr int NT = 1024;   // tokens
constexpr int E  = 8;      // experts
}

// ---------------- scratch (static device globals; no allocation) ------------
__device__ float g_G[2048 * 1024];     // routed SwiGLU output (fp32)
__device__ float g_Gs[1024 * 1024];    // shared-expert SwiGLU output
__device__ float g_ybuf[2048 * 1024];  // scaled routed outputs, indexed token*2+k
__device__ int   g_rowinfo[2048];      // segment pos -> token*2+k
__device__ int   g_sel[2048];
__device__ float g_wts[2048];
__device__ int   g_cnt[E];
__device__ int   g_off[E];
__device__ int   g_cnt2[E];

// ---------------- helpers ----------------------------------------------------
__device__ __forceinline__ uint32_t smem_u32(const void* p) {
  uint32_t a;
  asm("{ .reg .u64 t; cvta.to.shared.u64 t, %1; cvt.u32.u64 %0, t; }" : "=r"(a) : "l"(p));
  return a;
}
// fp32 -> tf32 (round-to-nearest-even on the 10-bit mantissa) as raw b32
__device__ __forceinline__ unsigned tf32r(float x) {
  unsigned u;
  asm("cvt.rna.tf32.f32 %0, %1;" : "=r"(u) : "f"(x));
  return u;
}
__device__ __forceinline__ void mma_tf32(float* c, const uint32_t* a, const uint32_t* b) {
  asm volatile(
      "mma.sync.aligned.m16n8k8.row.col.f32.tf32.tf32.f32 "
      "{%0,%1,%2,%3}, {%4,%5,%6,%7}, {%8,%9}, {%0,%1,%2,%3};"
      : "+f"(c[0]), "+f"(c[1]), "+f"(c[2]), "+f"(c[3])
      : "r"(a[0]), "r"(a[1]), "r"(a[2]), "r"(a[3]), "r"(b[0]), "r"(b[1]));
}

#define CP16(dst, src, sz) \
  asm volatile("cp.async.cg.shared.global [%0], [%1], 16, %2;" \
               :: "r"(dst), "l"(src), "r"(sz) : "memory")
#define CP_COMMIT() asm volatile("cp.async.commit_group;" ::: "memory")
#define CP_WAIT(n)  asm volatile("cp.async.wait_group %0;" :: "n"(n) : "memory")

// ---------------- routing kernels --------------------------------------------
__global__ void init_kernel() {
  const int t = threadIdx.x;
  if (t < E) { g_cnt[t] = 0; g_cnt2[t] = 0; }
}

__global__ __launch_bounds__(256) void router_kernel(
    const float* __restrict__ x, const float* __restrict__ rw,
    const float* __restrict__ bias) {
  const int n = blockIdx.x;
  const int tid = threadIdx.x;
  const float* xr = x + (size_t)n * 1024;

  float acc[8];
#pragma unroll
  for (int e = 0; e < 8; e++) acc[e] = 0.f;
  for (int d = tid; d < 1024; d += 256) {
    const float xv = xr[d];
    const float4* r = reinterpret_cast<const float4*>(rw + (size_t)d * 8);
    const float4 r0 = r[0], r1 = r[1];
    acc[0] += xv * r0.x; acc[1] += xv * r0.y;
    acc[2] += xv * r0.z; acc[3] += xv * r0.w;
    acc[4] += xv * r1.x; acc[5] += xv * r1.y;
    acc[6] += xv * r1.z; acc[7] += xv * r1.w;
  }
  __shared__ float red[8][256];
#pragma unroll
  for (int e = 0; e < 8; e++) red[e][tid] = acc[e];
  __syncthreads();
  for (int s = 128; s > 0; s >>= 1) {
    if (tid < s) {
#pragma unroll
      for (int e = 0; e < 8; e++) red[e][tid] += red[e][tid + s];
    }
    __syncthreads();
  }
  if (tid == 0) {
    float lg[8], sc[8];
    float m = -1e30f;
#pragma unroll
    for (int e = 0; e < 8; e++) { lg[e] = red[e][0]; m = fmaxf(m, lg[e]); }
    float s = 0.f;
#pragma unroll
    for (int e = 0; e < 8; e++) { sc[e] = expf(lg[e] - m); s += sc[e]; }
    const float inv = 1.f / s;
#pragma unroll
    for (int e = 0; e < 8; e++) sc[e] *= inv;
    int i0 = 0; float v0 = -1e30f;
#pragma unroll
    for (int e = 0; e < 8; e++) {
      const float v = sc[e] + bias[e];
      if (v > v0) { v0 = v; i0 = e; }
    }
    int i1 = -1; float v1 = -1e30f;
#pragma unroll
    for (int e = 0; e < 8; e++) {
      if (e == i0) continue;
      const float v = sc[e] + bias[e];
      if (v > v1) { v1 = v; i1 = e; }
    }
    g_sel[n * 2 + 0] = i0;  g_wts[n * 2 + 0] = sc[i0];
    g_sel[n * 2 + 1] = i1;  g_wts[n * 2 + 1] = sc[i1];
    atomicAdd(&g_cnt[i0], 1);
    atomicAdd(&g_cnt[i1], 1);
  }
}

__global__ void offsets_kernel() {
  int o = 0;
  for (int e = 0; e < E; e++) { g_off[e] = o; o += g_cnt[e]; }
}

__global__ void assign_kernel() {
  const int idx = blockIdx.x * 256 + threadIdx.x;
  if (idx < 2 * NT) {
    const int e = g_sel[idx];
    const int pos = g_off[e] + atomicAdd(&g_cnt2[e], 1);
    g_rowinfo[pos] = idx;
  }
}

// ---------------- GEMM 1+3 (tf32 mma, 3-stage cp.async) ----------------------
// Tile M=128, N=64 per matrix (w1 & w3), BK=32, 8 warps (4m x 2n), warp tile
// 32m x 32n per matrix. Raw fp32 staged via cp.async; cvt.rna at fragment load.
// Per-buffer words: A[128][36] @0, B1[32][72] @4608, B3 @6912; stride 9216 w.
// 3 stages, ONE __syncthreads per chunk.
__global__ __launch_bounds__(256, 2) void gemm13_tf(
    const float* __restrict__ x,
    const float* __restrict__ w1, const float* __restrict__ w3,
    const float* __restrict__ sw1, const float* __restrict__ sw3) {
  const int e = blockIdx.z;
  int cnt, off;
  const float *B1g, *B3g;
  float* Gout;
  if (e < E) {
    cnt = g_cnt[e]; off = g_off[e];
    B1g = w1 + (size_t)e * 1048576;
    B3g = w3 + (size_t)e * 1048576;
    Gout = g_G;
  } else {
    cnt = NT; off = 0; B1g = sw1; B3g = sw3; Gout = g_Gs;
  }
  const int row0 = blockIdx.y * 128;
  if (row0 >= cnt) return;
  const int col0 = blockIdx.x * 64;
  const int tid = threadIdx.x;
  const int lane = tid & 31, wid = tid >> 5;
  const int wm = wid & 3, wn = wid >> 2;

  extern __shared__ float sf[];
  __shared__ int rows_s[128];
  const uint32_t sb = smem_u32(sf);

  if (tid < 128) {
    const int r = row0 + tid;
    rows_s[tid] = (r < cnt) ? ((e < E) ? (g_rowinfo[off + r] >> 1) : r) : -1;
  }
  __syncthreads();

  // per-thread cp.async source descriptors (A: 4 segs; B1/B3: 2 segs each)
  const float* asrc[4];
  unsigned     asz[4];
  unsigned     adst[4];
#pragma unroll
  for (int p = 0; p < 4; p++) {
    const int i = tid + p * 256;
    const int ar = i >> 3, aseg = (i & 7) * 4;
    const int srow = rows_s[ar];
    asrc[p] = (srow >= 0 ? x + (size_t)srow * 1024 : x) + aseg;
    asz[p]  = (srow >= 0) ? 16u : 0u;
    adst[p] = (unsigned)(ar * 36 + aseg) * 4u;
  }
  unsigned bdst[2];
  const float* b1src[2];
  const float* b3src[2];
#pragma unroll
  for (int p = 0; p < 2; p++) {
    const int i = tid + p * 256;
    const int br = i >> 4, bseg = (i & 15) * 4;
    b1src[p] = B1g + (size_t)br * 1024 + col0 + bseg;
    b3src[p] = B3g + (size_t)br * 1024 + col0 + bseg;
    bdst[p] = (unsigned)(br * 72 + bseg) * 4u;
  }

  auto stage = [&](int k0, int b) {
    const unsigned bo = sb + (unsigned)b * 36864u;
#pragma unroll
    for (int p = 0; p < 4; p++) CP16(bo + adst[p], asrc[p] + k0, asz[p]);
#pragma unroll
    for (int p = 0; p < 2; p++) {
      CP16(bo + 18432u + bdst[p], b1src[p] + (size_t)k0 * 1024, 16u);
      CP16(bo + 27648u + bdst[p], b3src[p] + (size_t)k0 * 1024, 16u);
    }
  };

  float acc1[2][4][4] = {}, acc3[2][4][4] = {};
  const int lr = lane >> 2, lc = lane & 3;

  auto compute = [&](int b) {
    const float* bb = sf + b * 9216;
#pragma unroll
    for (int ks = 0; ks < 4; ks++) {
      uint32_t af[2][4];
#pragma unroll
      for (int mt = 0; mt < 2; mt++) {
        const float* ap = bb + (wm * 32 + mt * 16 + lr) * 36 + ks * 8 + lc;
        af[mt][0] = tf32r(ap[0]);
        af[mt][1] = tf32r(ap[8 * 36]);
        af[mt][2] = tf32r(ap[4]);
        af[mt][3] = tf32r(ap[8 * 36 + 4]);
      }
      const int bn = wn * 32 + lr;
      const float* b1p = bb + 4608 + (ks * 8 + lc) * 72 + bn;
      const float* b3p = bb + 6912 + (ks * 8 + lc) * 72 + bn;
#pragma unroll
      for (int nt = 0; nt < 4; nt++) {
        uint32_t bf[2];
        bf[0] = tf32r(b1p[nt * 8]);
        bf[1] = tf32r(b1p[nt * 8 + 4 * 72]);
#pragma unroll
        for (int mt = 0; mt < 2; mt++) mma_tf32(acc1[mt][nt], af[mt], bf);
        bf[0] = tf32r(b3p[nt * 8]);
        bf[1] = tf32r(b3p[nt * 8 + 4 * 72]);
#pragma unroll
        for (int mt = 0; mt < 2; mt++) mma_tf32(acc3[mt][nt], af[mt], bf);
      }
    }
  };

  // 3-stage pipeline, one barrier per chunk.
  stage(0, 0);  CP_COMMIT();
  stage(32, 1); CP_COMMIT();
  for (int c = 0; c < 32; c++) {
    CP_WAIT(1);          // stage c resident (c+1 may still be in flight)
    __syncthreads();     // all warps done with compute(c-1); buf (c+2)%3 free
    if (c < 30) {
      stage((c + 2) * 32, (c + 2) % 3);
      CP_COMMIT();
    }
    compute(c % 3);
  }

  // epilogue: g = silu(h1) * h3
#pragma unroll
  for (int mt = 0; mt < 2; mt++)
#pragma unroll
    for (int nt = 0; nt < 4; nt++)
#pragma unroll
      for (int rh = 0; rh < 2; rh++) {
        const int r = row0 + wm * 32 + mt * 16 + lr + rh * 8;
        if (r < cnt) {
          const float h1a = acc1[mt][nt][rh * 2],     h3a = acc3[mt][nt][rh * 2];
          const float h1b = acc1[mt][nt][rh * 2 + 1], h3b = acc3[mt][nt][rh * 2 + 1];
          const float g0 = h1a / (1.f + __expf(-h1a)) * h3a;
          const float g1 = h1b / (1.f + __expf(-h1b)) * h3b;
          const int col = col0 + wn * 32 + nt * 8 + lc * 2;
          *(float2*)(Gout + (size_t)(off + r) * 1024 + col) = make_float2(g0, g1);
        }
      }
}

// ---------------- GEMM 2 (tf32 mma, 3-stage cp.async): Y = G @ W2 ------------
// Tile M=128, N=128, BK=32, warp tile 32m x 64n. Per-buffer words: A[128][36]
// @0, B[32][136] @4608; stride 8960 w (35840 B). 3 stages, one sync per chunk.
__global__ __launch_bounds__(256, 2) void gemm2_tf(
    const float* __restrict__ w2, const float* __restrict__ sw2,
    float* __restrict__ out) {
  const int e = blockIdx.z;
  int cnt, off, rowcap;
  const float* Bg;
  const float* Asrc;
  if (e < E) {
    cnt = g_cnt[e]; off = g_off[e];
    Bg = w2 + (size_t)e * 1048576;
    Asrc = g_G; rowcap = 2047;
  } else {
    cnt = NT; off = 0; Bg = sw2; Asrc = g_Gs; rowcap = 1023;
  }
  const int row0 = blockIdx.y * 128;
  if (row0 >= cnt) return;
  const int col0 = blockIdx.x * 128;
  const int tid = threadIdx.x;
  const int lane = tid & 31, wid = tid >> 5;
  const int wm = wid & 3, wn = wid >> 2;

  extern __shared__ float sf[];
  __shared__ int   rowdst_s[128];
  __shared__ float wt_s[128];
  const uint32_t sb = smem_u32(sf);

  if (tid < 128) {
    if (e < E) {
      int idx = off + row0 + tid; if (idx > 2047) idx = 2047;
      const int t2k = g_rowinfo[idx];
      rowdst_s[tid] = t2k;
      wt_s[tid] = g_wts[t2k];
    } else {
      rowdst_s[tid] = row0 + tid;
      wt_s[tid] = 1.f;
    }
  }
  __syncthreads();

  const float* asrc[4];
  unsigned     adst[4];
#pragma unroll
  for (int p = 0; p < 4; p++) {
    const int i = tid + p * 256;
    const int ar = i >> 3, aseg = (i & 7) * 4;
    int arow = off + row0 + ar; if (arow > rowcap) arow = rowcap;
    asrc[p] = Asrc + (size_t)arow * 1024 + aseg;
    adst[p] = (unsigned)(ar * 36 + aseg) * 4u;
  }
  const float* bsrc[4];
  unsigned     bdst[4];
#pragma unroll
  for (int p = 0; p < 4; p++) {
    const int i = tid + p * 256;
    const int br = i >> 5, bseg = (i & 31) * 4;
    bsrc[p] = Bg + (size_t)br * 1024 + col0 + bseg;
    bdst[p] = (unsigned)(br * 136 + bseg) * 4u;
  }

  auto stage = [&](int k0, int b) {
    const unsigned bo = sb + (unsigned)b * 35840u;
#pragma unroll
    for (int p = 0; p < 4; p++) CP16(bo + adst[p], asrc[p] + k0, 16u);
#pragma unroll
    for (int p = 0; p < 4; p++) CP16(bo + 18432u + bdst[p], bsrc[p] + (size_t)k0 * 1024, 16u);
  };

  float acc[2][8][4] = {};
  const int lr = lane >> 2, lc = lane & 3;

  auto compute = [&](int b) {
    const float* bb = sf + b * 8960;
#pragma unroll
    for (int ks = 0; ks < 4; ks++) {
      uint32_t af[2][4];
#pragma unroll
      for (int mt = 0; mt < 2; mt++) {
        const float* ap = bb + (wm * 32 + mt * 16 + lr) * 36 + ks * 8 + lc;
        af[mt][0] = tf32r(ap[0]);
        af[mt][1] = tf32r(ap[8 * 36]);
        af[mt][2] = tf32r(ap[4]);
        af[mt][3] = tf32r(ap[8 * 36 + 4]);
      }
      const float* bp = bb + 4608 + (ks * 8 + lc) * 136 + wn * 64 + lr;
#pragma unroll
      for (int nt = 0; nt < 8; nt++) {
        uint32_t bf[2];
        bf[0] = tf32r(bp[nt * 8]);
        bf[1] = tf32r(bp[nt * 8 + 4 * 136]);
#pragma unroll
        for (int mt = 0; mt < 2; mt++) mma_tf32(acc[mt][nt], af[mt], bf);
      }
    }
  };

  stage(0, 0);  CP_COMMIT();
  stage(32, 1); CP_COMMIT();
  for (int c = 0; c < 32; c++) {
    CP_WAIT(1);
    __syncthreads();
    if (c < 30) {
      stage((c + 2) * 32, (c + 2) % 3);
      CP_COMMIT();
    }
    compute(c % 3);
  }

#pragma unroll
  for (int mt = 0; mt < 2; mt++)
#pragma unroll
    for (int nt = 0; nt < 8; nt++)
#pragma unroll
      for (int rh = 0; rh < 2; rh++) {
        const int rloc = wm * 32 + mt * 16 + lr + rh * 8;
        if (row0 + rloc < cnt) {
          const float wt = wt_s[rloc];
          const float y0 = wt * acc[mt][nt][rh * 2];
          const float y1 = wt * acc[mt][nt][rh * 2 + 1];
          const int col = col0 + wn * 64 + nt * 8 + lc * 2;
          float* dst = (e < E) ? (g_ybuf + (size_t)rowdst_s[rloc] * 1024 + col)
                               : (out + (size_t)rowdst_s[rloc] * 1024 + col);
          *(float2*)dst = make_float2(y0, y1);
        }
      }
}

// ---------------- combine: out += y0 + y1 (fixed order) ----------------------
__global__ __launch_bounds__(256) void combine_kernel(float* __restrict__ out) {
  const int i = blockIdx.x * 256 + threadIdx.x;
  const int n = i >> 8;
  const int c = i & 255;
  float4 o = reinterpret_cast<float4*>(out)[i];
  const float4* y = reinterpret_cast<const float4*>(g_ybuf);
  const float4 a = y[(size_t)(2 * n + 0) * 256 + c];
  const float4 b = y[(size_t)(2 * n + 1) * 256 + c];
  o.x += a.x + b.x;
  o.y += a.y + b.y;
  o.z += a.z + b.z;
  o.w += a.w + b.w;
  reinterpret_cast<float4*>(out)[i] = o;
}

// ---------------- launch -----------------------------------------------------
extern "C" void kernel_launch(void* const* d_in, const int* in_sizes, int n_in,
                              void* d_out, int out_size) {
  const float* x   = (const float*)d_in[0];
  const float* rw  = (const float*)d_in[1];
  const float* eb  = (const float*)d_in[2];
  const float* w1  = (const float*)d_in[3];
  const float* w2  = (const float*)d_in[4];
  const float* w3  = (const float*)d_in[5];
  const float* sw1 = (const float*)d_in[6];
  const float* sw2 = (const float*)d_in[7];
  const float* sw3 = (const float*)d_in[8];
  float* out = (float*)d_out;

  const int smem13 = 3 * 36864;  // 110592 B
  const int smem2  = 3 * 35840;  // 107520 B
  cudaFuncSetAttribute(gemm13_tf, cudaFuncAttributeMaxDynamicSharedMemorySize, smem13);
  cudaFuncSetAttribute(gemm2_tf,  cudaFuncAttributeMaxDynamicSharedMemorySize, smem2);

  init_kernel<<<1, 32>>>();
  router_kernel<<<NT, 256>>>(x, rw, eb);
  offsets_kernel<<<1, 1>>>();
  assign_kernel<<<(2 * NT + 255) / 256, 256>>>();

  // z: 0..7 routed experts, 8 = shared expert.
  gemm13_tf<<<dim3(16, 8, 9), 256, smem13>>>(x, w1, w3, sw1, sw3);
  gemm2_tf<<<dim3(8, 8, 9), 256, smem2>>>(w2, sw2, out);

  combine_kernel<<<(NT * 1024 / 4) / 256, 256>>>(out);
}